// round 17
// baseline (speedup 1.0000x reference)
#include <cuda_runtime.h>
#include <cuda_fp16.h>
#include <math.h>
#include <stdint.h>

#define LL 5
#define BB 256
#define HH 512
#define GG 2048
#define SSTEPS 128
#define VV 32000
#define KTOT 1024

#define NCTA 296       // exactly 2 CTAs per SM on 148 SMs
#define NTHR 256
#define KC 64
#define NCHL 8         // chunks per task (K=512)
#define NCHO 8
#define NSTG 4
#define NDIAG (SSTEPS + LL - 1)   // 132

// dynamic SMEM layout (bytes)
#define SM_TBASE 2048
#define SM_BUF   24576 // A 16K (128x64 fp16) | W 8K (64x64 fp16)
#define OFF_A 0
#define OFF_W 16384
#define SMEM_TOTAL (SM_TBASE + NSTG*SM_BUF)   // 100352 -> 2 CTAs/SM
#define SM_GS  SM_TBASE                        // gs overlays stage buffers (output epilogue only)
#define GS_STRIDE 66

// ---- persistent device scratch ----
__device__ __align__(16) __half g_w[LL*GG*KTOT];
__device__ __align__(16) __half g_wo[(size_t)VV*HH];
__device__ __align__(16) __half g_e[(size_t)SSTEPS*BB*HH];
__device__ __align__(16) __half g_h[2*LL*BB*HH];
__device__ float    g_c[(size_t)LL*BB*HH];
__device__ float    g_bias[LL*GG];
__device__ __align__(16) float g_part[(size_t)640*NTHR*32];   // [task id][tid][32]
__device__ unsigned g_tick[NDIAG];
__device__ unsigned g_done[NDIAG*320];
__device__ unsigned g_bar_count;
__device__ unsigned g_bar_gen;

// ================= helpers =================
#define SWZ128(o) ((o) ^ (((o) >> 3) & 0x70))

__device__ __forceinline__ uint32_t smem_u32(const void* p) {
    uint32_t a;
    asm("{ .reg .u64 t; cvta.to.shared.u64 t, %1; cvt.u32.u64 %0, t; }" : "=r"(a) : "l"(p));
    return a;
}
__device__ __forceinline__ void cp16(uint32_t d, const void* s) {
    asm volatile("cp.async.cg.shared.global [%0], [%1], 16;" :: "r"(d), "l"(s));
}
__device__ __forceinline__ void cp_commit() { asm volatile("cp.async.commit_group;" ::: "memory"); }
__device__ __forceinline__ void cp_wait2()  { asm volatile("cp.async.wait_group 2;" ::: "memory"); }
__device__ __forceinline__ void cp_wait1()  { asm volatile("cp.async.wait_group 1;" ::: "memory"); }
__device__ __forceinline__ void cp_wait0()  { asm volatile("cp.async.wait_group 0;" ::: "memory"); }

__device__ __forceinline__ void ldsm4(uint32_t* r, uint32_t a) {
    asm volatile("ldmatrix.sync.aligned.m8n8.x4.shared.b16 {%0,%1,%2,%3}, [%4];"
        : "=r"(r[0]), "=r"(r[1]), "=r"(r[2]), "=r"(r[3]) : "r"(a));
}
__device__ __forceinline__ void mma16816(float* d, const uint32_t* a, const uint32_t* b) {
    asm volatile("mma.sync.aligned.m16n8k16.row.col.f32.f16.f16.f32 "
        "{%0,%1,%2,%3}, {%4,%5,%6,%7}, {%8,%9}, {%0,%1,%2,%3};"
        : "+f"(d[0]), "+f"(d[1]), "+f"(d[2]), "+f"(d[3])
        : "r"(a[0]), "r"(a[1]), "r"(a[2]), "r"(a[3]), "r"(b[0]), "r"(b[1]));
}
__device__ __forceinline__ float4 ldcg4(const float* p) {
    float4 v;
    asm volatile("ld.global.cg.v4.f32 {%0,%1,%2,%3}, [%4];"
        : "=f"(v.x), "=f"(v.y), "=f"(v.z), "=f"(v.w) : "l"(p));
    return v;
}

__device__ __forceinline__ float sigf(float v)   { return 1.0f / (1.0f + __expf(-v)); }
__device__ __forceinline__ float tanhft(float v) { return 2.0f / (1.0f + __expf(-2.0f * v)) - 1.0f; }

__device__ __forceinline__ void grid_sync() {
    __syncthreads();
    if (threadIdx.x == 0) {
        __threadfence();
        unsigned gen = *((volatile unsigned*)&g_bar_gen);
        if (atomicAdd(&g_bar_count, 1u) == NCTA - 1u) {
            atomicExch(&g_bar_count, 0u);
            __threadfence();
            atomicAdd(&g_bar_gen, 1u);
        } else {
            while (*((volatile unsigned*)&g_bar_gen) == gen) { __nanosleep(32); }
        }
        __threadfence();
    }
    __syncthreads();
}

// cp.async one chunk (256 threads): A 128x64 fp16 + W 64x64 fp16, SW128 swizzled
__device__ __forceinline__ void issue_chunk(uint32_t tb,
    const __half* a, const __half* w, int wstride, int tid)
{
    #pragma unroll
    for (int j = 0; j < 4; ++j) {
        int g = tid + NTHR * j, m = g >> 3, q = g & 7;
        uint32_t so = SWZ128((uint32_t)(m * 128 + q * 16));
        cp16(tb + OFF_A + so, a + (size_t)m * HH + q * 8);
    }
    #pragma unroll
    for (int j = 0; j < 2; ++j) {
        int g = tid + NTHR * j, m = g >> 3, q = g & 7;
        uint32_t so = SWZ128((uint32_t)(m * 128 + q * 16));
        cp16(tb + OFF_W + so, w + (size_t)m * wstride + q * 8);
    }
    cp_commit();
}

// task id encodes (cell<<7)|(kh<<6)|(mq<<5)|nb   (mq: batch half of 128 rows)
__device__ __forceinline__ void issue_task_chunk(uint32_t tb, int id, int k,
                                                 int dg, int l_lo, int tid)
{
    const int nb = id & 31, mqv = (id >> 5) & 1, khv = (id >> 6) & 1, cell = id >> 7;
    const int l = l_lo + cell, t = dg - l;
    const int cur = t & 1, prev = cur ^ 1;
    const size_t row0 = (size_t)(mqv * 128) * HH;
    const __half* a;
    if (khv == 0) {
        if (l == 0) a = g_e + (size_t)t * BB * HH + row0;
        else        a = g_h + ((size_t)cur * LL + (l - 1)) * BB * HH + row0;
    } else {
        a = g_h + ((size_t)prev * LL + l) * BB * HH + row0;
    }
    const __half* w = g_w + ((size_t)l * GG + nb * 64) * KTOT + khv * (NCHL * KC);
    issue_chunk(tb, a + k * KC, w + k * KC, KTOT, tid);
}

// compute one resident chunk into d[2][4][4]. 8 warps = 4m x 2n, warp tile 32x32.
__device__ __forceinline__ void compute_chunk(float d[2][4][4], uint32_t tb,
    const uint32_t* arow128, const uint32_t* brow128, int mask, int a_kb, int b_kb)
{
    #pragma unroll
    for (int s = 0; s < 4; ++s) {
        uint32_t a_[2][4], w_[2][4];
        const uint32_t akx = (uint32_t)((32 * s + a_kb) ^ mask);
        const uint32_t bkx = (uint32_t)((32 * s + b_kb) ^ mask);
        #pragma unroll
        for (int mi = 0; mi < 2; ++mi)
            ldsm4(a_[mi], tb + OFF_A + arow128[mi] + akx);
        #pragma unroll
        for (int nj = 0; nj < 2; ++nj)
            ldsm4(w_[nj], tb + OFF_W + brow128[nj] + bkx);
        #pragma unroll
        for (int mi = 0; mi < 2; ++mi)
            #pragma unroll
            for (int nj = 0; nj < 2; ++nj)
                #pragma unroll
                for (int h = 0; h < 2; ++h)
                    mma16816(d[mi][nj * 2 + h], a_[mi], &w_[nj][h * 2]);
    }
}

// end-of-task: write partials; second finisher of the kh-pair activates inline
__device__ void finish_task(float d[2][4][4], int id, int dg, int l_lo, int tid,
                            volatile int* done_old_s)
{
    float* mp = g_part + ((size_t)id * NTHR + tid) * 32;
    #pragma unroll
    for (int mi = 0; mi < 2; ++mi)
        #pragma unroll
        for (int ni = 0; ni < 4; ++ni)
            *(float4*)(mp + (mi * 4 + ni) * 4) =
                make_float4(d[mi][ni][0], d[mi][ni][1], d[mi][ni][2], d[mi][ni][3]);
    __threadfence();
    __syncthreads();
    const int nb = id & 31, mqv = (id >> 5) & 1, cell = id >> 7;
    if (tid == 0)
        *done_old_s = (int)atomicAdd(&g_done[dg * 320 + (cell * 2 + mqv) * 32 + nb], 1u);
    __syncthreads();
    if (*done_old_s == 1) {
        const float* pp = g_part + ((size_t)(id ^ 64) * NTHR + tid) * 32;
        const int l = l_lo + cell;
        const int cur = (dg - l) & 1;
        const int lane = tid & 31, wm = (tid >> 5) & 3, wn = tid >> 7;
        const int trow = wm * 32 + (lane >> 2);
        #pragma unroll
        for (int mi = 0; mi < 2; ++mi) {
            float f[4][4];
            #pragma unroll
            for (int ni = 0; ni < 4; ++ni) {
                const float4 p4 = ldcg4(pp + (mi * 4 + ni) * 4);
                f[ni][0] = d[mi][ni][0] + p4.x; f[ni][1] = d[mi][ni][1] + p4.y;
                f[ni][2] = d[mi][ni][2] + p4.z; f[ni][3] = d[mi][ni][3] + p4.w;
            }
            #pragma unroll
            for (int q = 0; q < 2; ++q) {
                const int cb = wn * 32 + q * 16 + (lane & 3) * 2;
                const int unit = (lane & 3) + 4 * (wn * 2 + q);
                const float b0 = g_bias[l * GG + nb * 64 + cb];
                const float b1 = g_bias[l * GG + nb * 64 + cb + 1];
                const float b2 = g_bias[l * GG + nb * 64 + cb + 8];
                const float b3 = g_bias[l * GG + nb * 64 + cb + 9];
                #pragma unroll
                for (int rr = 0; rr < 2; ++rr) {
                    const int row = mqv * 128 + trow + mi * 16 + rr * 8;
                    const float gi = f[q * 2 + 0][rr * 2 + 0] + b0;
                    const float gf = f[q * 2 + 0][rr * 2 + 1] + b1;
                    const float gg = f[q * 2 + 1][rr * 2 + 0] + b2;
                    const float go = f[q * 2 + 1][rr * 2 + 1] + b3;
                    const size_t ci = ((size_t)l * BB + row) * HH + nb * 16 + unit;
                    const float cn = sigf(gf) * g_c[ci] + sigf(gi) * tanhft(gg);
                    g_c[ci] = cn;
                    const float hv = sigf(go) * tanhft(cn);
                    g_h[((size_t)cur * LL + l) * BB * HH + (size_t)row * HH + nb * 16 + unit]
                        = __float2half(hv);
                }
            }
        }
    }
    #pragma unroll
    for (int mi = 0; mi < 2; ++mi)
        #pragma unroll
        for (int ni = 0; ni < 4; ++ni)
            d[mi][ni][0] = d[mi][ni][1] = d[mi][ni][2] = d[mi][ni][3] = 0.0f;
}

// standalone 4-stage pipelined GEMM (output stage)
__device__ void gemm_mma(float d[2][4][4], uint32_t sb, int tid, int nch,
    const __half* a0, const __half* w0, int wstride,
    const uint32_t* arow128, const uint32_t* brow128, int mask, int a_kb, int b_kb)
{
    #pragma unroll
    for (int mi = 0; mi < 2; ++mi)
        #pragma unroll
        for (int ni = 0; ni < 4; ++ni)
            d[mi][ni][0] = d[mi][ni][1] = d[mi][ni][2] = d[mi][ni][3] = 0.0f;
    #pragma unroll
    for (int p = 0; p < NSTG - 1; ++p)
        if (p < nch)
            issue_chunk(sb + SM_TBASE + p * SM_BUF, a0 + p * KC, w0 + p * KC, wstride, tid);
    #pragma unroll 1
    for (int c = 0; c < nch; ++c) {
        const int rem = nch - 1 - c;
        if (rem >= 2) cp_wait2(); else if (rem == 1) cp_wait1(); else cp_wait0();
        __syncthreads();
        if (c + NSTG - 1 < nch) {
            const int c2 = c + NSTG - 1;
            issue_chunk(sb + SM_TBASE + (c2 & (NSTG - 1)) * SM_BUF,
                        a0 + c2 * KC, w0 + c2 * KC, wstride, tid);
        }
        compute_chunk(d, sb + SM_TBASE + (c & (NSTG - 1)) * SM_BUF,
                      arow128, brow128, mask, a_kb, b_kb);
    }
}

// store accumulators into padded fp32 tile gs[128][GS_STRIDE]
__device__ __forceinline__ void store_gates(float* gs, const float d[2][4][4], int tid) {
    const int lane = tid & 31, wm = (tid >> 5) & 3, wn = tid >> 7;
    const int trow = wm * 32 + (lane >> 2);
    #pragma unroll
    for (int mi = 0; mi < 2; ++mi)
        #pragma unroll
        for (int ni = 0; ni < 4; ++ni) {
            const int r0 = trow + mi * 16;
            const int cc = wn * 32 + ni * 8 + (lane & 3) * 2;
            *(float2*)(gs + r0 * GS_STRIDE + cc)       = make_float2(d[mi][ni][0], d[mi][ni][1]);
            *(float2*)(gs + (r0 + 8) * GS_STRIDE + cc) = make_float2(d[mi][ni][2], d[mi][ni][3]);
        }
}

// ================= prep kernels =================
// 64-col tile permutation: col c -> gate (c&1)|((c>>3&1)<<1), unit ((c>>1)&3)|((c>>4&3)<<2)
__global__ void prep_w(const float* __restrict__ Wih, const float* __restrict__ Whh) {
    for (int idx = blockIdx.x * blockDim.x + threadIdx.x; idx < LL * GG * KTOT; idx += gridDim.x * blockDim.x) {
        int k = idx & 1023, n = (idx >> 10) & 2047, l = idx >> 21;
        int gate = (n & 1) | (((n >> 3) & 1) << 1);
        int unit = ((n >> 1) & 3) | (((n >> 4) & 3) << 2);
        int src = gate * HH + (n >> 6) * 16 + unit;
        float v = (k < HH) ? Wih[((size_t)l * GG + src) * HH + k]
                           : Whh[((size_t)l * GG + src) * HH + (k - HH)];
        g_w[idx] = __float2half(v);
    }
}
__global__ void prep_b(const float* __restrict__ bih, const float* __restrict__ bhh) {
    for (int idx = blockIdx.x * blockDim.x + threadIdx.x; idx < LL * GG; idx += gridDim.x * blockDim.x) {
        int n = idx & 2047, l = idx >> 11;
        int c = n & 63, tile = n >> 6;
        int gate = (c & 1) | (((c >> 3) & 1) << 1);
        int unit = ((c >> 1) & 3) | (((c >> 4) & 3) << 2);
        int src = gate * HH + tile * 16 + unit;
        g_bias[idx] = bih[l * GG + src] + bhh[l * GG + src];
    }
}
__global__ void prep_wo(const float* __restrict__ Wout) {
    for (size_t idx = blockIdx.x * blockDim.x + threadIdx.x; idx < (size_t)VV * HH; idx += (size_t)gridDim.x * blockDim.x)
        g_wo[idx] = __float2half(Wout[idx]);
}
__global__ void prep_e(const int* __restrict__ x, const float* __restrict__ emb) {
    for (int idx = blockIdx.x * blockDim.x + threadIdx.x; idx < SSTEPS * BB * HH; idx += gridDim.x * blockDim.x) {
        int k = idx & 511, b = (idx >> 9) & 255, t = idx >> 17;
        int tok = x[t * BB + b];   // torch .view(S,B,-1) reinterpretation
        g_e[idx] = __float2half(emb[(size_t)tok * HH + k]);
    }
}

// ================= main persistent kernel =================
__global__ void __launch_bounds__(NTHR, 2)
lstm_mma(const float* __restrict__ h0, const float* __restrict__ c0,
         const float* __restrict__ bout, float* __restrict__ out)
{
    extern __shared__ __align__(1024) char smem[];
    __shared__ int task_q[8];
    __shared__ int done_old_s;
    const uint32_t sb = smem_u32(smem);
    const int tid = threadIdx.x, bid = blockIdx.x;

    const int lane = tid & 31, wid = tid >> 5;
    const int wm = wid & 3, wn = wid >> 2;           // 4m x 2n
    const int mask = (lane & 7) << 4;
    const int a_row = ((lane >> 3) & 1) * 8 + (lane & 7);
    const int a_kb  = ((lane >> 4) & 1) * 16;
    const int b_row = ((lane >> 4) & 1) * 8 + (lane & 7);
    const int b_kb  = ((lane >> 3) & 1) * 16;
    uint32_t arow128[2], brow128[2];
    #pragma unroll
    for (int i = 0; i < 2; ++i) {
        arow128[i] = (uint32_t)((wm * 32 + i * 16 + a_row) * 128);
        brow128[i] = (uint32_t)((wn * 32 + i * 16 + b_row) * 128);
    }

    // ---- init: counters, c, h0 ----
    for (int i = bid * NTHR + tid; i < NDIAG; i += NCTA * NTHR) g_tick[i] = 0u;
    for (int i = bid * NTHR + tid; i < NDIAG * 320; i += NCTA * NTHR) g_done[i] = 0u;
    for (int i = bid * NTHR + tid; i < LL * BB * HH; i += NCTA * NTHR) {
        g_c[i] = c0[i];
        g_h[LL * BB * HH + i] = __float2half(h0[i]);
    }
    grid_sync();

    float d[2][4][4];

    // ======== wavefront over diagonals, work-stealing within each ========
    #pragma unroll 1
    for (int dg = 0; dg < NDIAG; ++dg) {
        const int l_lo = (dg > SSTEPS - 1) ? (dg - (SSTEPS - 1)) : 0;
        const int l_hi = (dg < LL - 1) ? dg : (LL - 1);
        const int ntask = (l_hi - l_lo + 1) << 7;   // ncells * 128

        if (tid == 0) task_q[0] = (int)atomicAdd(&g_tick[dg], 1u);
        __syncthreads();

        int np = 0, cp = 0;
        #pragma unroll
        for (int i = 0; i < NSTG - 1; ++i) {
            const int id0 = task_q[(np >> 3) & 7];
            if (id0 < ntask) {
                issue_task_chunk(sb + SM_TBASE + (np & 3) * SM_BUF, id0, np & 7, dg, l_lo, tid);
                np++;
            }
        }
        #pragma unroll
        for (int mi = 0; mi < 2; ++mi)
            #pragma unroll
            for (int ni = 0; ni < 4; ++ni)
                d[mi][ni][0] = d[mi][ni][1] = d[mi][ni][2] = d[mi][ni][3] = 0.0f;

        #pragma unroll 1
        while (true) {
            const int s = cp >> 3;
            const int id = task_q[s & 7];
            if (id >= ntask) break;
            const int infl = np - cp;
            if (infl >= 3) cp_wait2(); else if (infl == 2) cp_wait1(); else cp_wait0();
            __syncthreads();
            if ((cp & 7) == 0 && tid == 0)
                task_q[(s + 1) & 7] = (int)atomicAdd(&g_tick[dg], 1u);
            {
                const int id2 = task_q[(np >> 3) & 7];
                if (id2 < ntask) {
                    issue_task_chunk(sb + SM_TBASE + (np & 3) * SM_BUF, id2, np & 7, dg, l_lo, tid);
                    np++;
                }
            }
            compute_chunk(d, sb + SM_TBASE + (cp & 3) * SM_BUF,
                          arow128, brow128, mask, a_kb, b_kb);
            if ((cp & 7) == 7)
                finish_task(d, id, dg, l_lo, tid, &done_old_s);
            cp++;
        }
        grid_sync();   // diagonal complete: h visible chip-wide
    }

    // ---- output GEMM: logits 256x32000, K=512 -> 2 x 500 = 1000 tiles of 128x64 ----
    float* gs = (float*)(smem + SM_GS);
    const size_t hf = ((size_t)((SSTEPS - 1) & 1) * LL + (LL - 1)) * BB * HH;
    #pragma unroll 1
    for (int tt = bid; tt < 1000; tt += NCTA) {
        const int b0 = (tt / 500) * 128;
        const int v0 = (tt % 500) * 64;
        gemm_mma(d, sb, tid, NCHO,
                 g_h + hf + (size_t)b0 * HH, g_wo + (size_t)v0 * HH, HH,
                 arow128, brow128, mask, a_kb, b_kb);
        store_gates(gs, d, tid);
        __syncthreads();
        {
            const int row = tid >> 1;
            const int c0c = (tid & 1) * 32;
            const float* gr = gs + row * GS_STRIDE + c0c;
            float* op = out + (size_t)(b0 + row) * VV + v0 + c0c;
            #pragma unroll
            for (int c4 = 0; c4 < 8; ++c4) {
                float4 s4;
                s4.x = gr[4*c4+0] + bout[v0 + c0c + 4*c4+0];
                s4.y = gr[4*c4+1] + bout[v0 + c0c + 4*c4+1];
                s4.z = gr[4*c4+2] + bout[v0 + c0c + 4*c4+2];
                s4.w = gr[4*c4+3] + bout[v0 + c0c + 4*c4+3];
                *(float4*)(op + 4*c4) = s4;
            }
        }
        __syncthreads();
    }
}

extern "C" void kernel_launch(void* const* d_in, const int* in_sizes, int n_in,
                              void* d_out, int out_size) {
    (void)in_sizes; (void)n_in; (void)out_size;
    prep_w<<<2048, 256>>>((const float*)d_in[4], (const float*)d_in[5]);
    prep_b<<<40, 256>>>((const float*)d_in[6], (const float*)d_in[7]);
    prep_wo<<<2048, 256>>>((const float*)d_in[8]);
    prep_e<<<2048, 256>>>((const int*)d_in[0], (const float*)d_in[3]);
    cudaFuncSetAttribute(lstm_mma, cudaFuncAttributeMaxDynamicSharedMemorySize, SMEM_TOTAL);
    lstm_mma<<<NCTA, NTHR, SMEM_TOTAL>>>(
        (const float*)d_in[1],   // h0
        (const float*)d_in[2],   // c0
        (const float*)d_in[9],   // b_out
        (float*)d_out);
}